// round 7
// baseline (speedup 1.0000x reference)
#include <cuda_runtime.h>
#include <stdint.h>
#include <math.h>

#define NB        50
#define NF_DIST   1225          // 50*49/2
#define NF_ANG    48
#define NF_DIH    47
#define NFEAT     (NF_DIST + NF_ANG + 2*NF_DIH)   // 1367

#define OFF_ANG   NF_DIST                 // 1225
#define OFF_DCOS  (NF_DIST + NF_ANG)      // 1273
#define OFF_DSIN  (OFF_DCOS + NF_DIH)     // 1320

// 7 groups of 7 rows: inc0 = 7g+1, tasks per group = 50 - inc0.
// 49+42+35+28+21+14+7 = 196
#define NTASK     196
#define T_ANG0    224           // angles on warp 7
#define T_DIH0    288           // dihedrals on warp 9
#define NTHREADS  352

// Task: thread owns bead i, sweeps rows inc0..inc0+6.
// Packed: i (bits 0-5) | inc0 (bits 6-11) | f0 = C(inc0-1) (bits 12+).
struct TaskTable { uint32_t v[NTASK]; };
constexpr TaskTable make_tasks() {
    TaskTable t{};
    int n = 0;
    for (int g = 0; g < 7; ++g) {
        const int inc0 = 7 * g + 1;
        const int f0   = (inc0 - 1) * (100 - inc0) / 2;
        for (int i = 0; i < NB - inc0; ++i)
            t.v[n++] = (uint32_t)(i | (inc0 << 6) | (f0 << 12));
    }
    return t;
}
__device__ constexpr TaskTable g_tasks = make_tasks();

__device__ __forceinline__ float fast_sqrt(float x) {
    float r;
    asm("sqrt.approx.f32 %0, %1;" : "=f"(r) : "f"(x));
    return r;
}

__global__ __launch_bounds__(NTHREADS)
void protein_feat_kernel(const float* __restrict__ data,
                         float* __restrict__ out)
{
    // Flat coords: x[i]=sraw[3i], y=3i+1, z=3i+2. Stride-3 LDS conflict-free.
    __shared__ float sraw[NB * 3];

    const int frame = blockIdx.x;
    const int tid   = threadIdx.x;

    const float* p = data + (size_t)frame * NB * 3;
    if (tid < NB * 3) sraw[tid] = p[tid];
    __syncthreads();

    float* o = out + (size_t)frame * NFEAT;

    if (tid < NTASK) {
        // ---- distances: bead i vs beads i+inc0 .. i+inc0+6 ----
        const uint32_t tv = g_tasks.v[tid];
        const int i       = tv & 63;
        const int inc0    = (tv >> 6) & 63;
        const int rl      = NB - inc0;       // length of first row in group
        int f             = (int)(tv >> 12) + i;
        int j             = i + inc0;

        const int i3 = 3 * i;
        const float ax = sraw[i3 + 0];
        const float ay = sraw[i3 + 1];
        const float az = sraw[i3 + 2];

        #pragma unroll
        for (int k = 0; k < 7; ++k) {
            if (j < NB) {
                const int j3 = 3 * j;
                const float dx = sraw[j3 + 0] - ax;
                const float dy = sraw[j3 + 1] - ay;
                const float dz = sraw[j3 + 2] - az;
                o[f] = fast_sqrt(fmaf(dx, dx, fmaf(dy, dy, dz * dz)));
            }
            f += rl - k;   // next row is one shorter
            ++j;
        }
    }
    else if (tid >= T_ANG0 && tid < T_ANG0 + NF_ANG) {
        // ---- angles: warp 7 ----
        const int a3 = (tid - T_ANG0) * 3;
        const float b1x = sraw[a3 + 0] - sraw[a3 + 3];
        const float b1y = sraw[a3 + 1] - sraw[a3 + 4];
        const float b1z = sraw[a3 + 2] - sraw[a3 + 5];
        const float b2x = sraw[a3 + 6] - sraw[a3 + 3];
        const float b2y = sraw[a3 + 7] - sraw[a3 + 4];
        const float b2z = sraw[a3 + 8] - sraw[a3 + 5];

        const float dot = fmaf(b1x, b2x, fmaf(b1y, b2y, b1z * b2z));
        const float n1  = fmaf(b1x, b1x, fmaf(b1y, b1y, b1z * b1z));
        const float n2  = fmaf(b2x, b2x, fmaf(b2y, b2y, b2z * b2z));
        float ct = dot * rsqrtf(n1 * n2);
        ct = fminf(1.0f, fmaxf(-1.0f, ct));
        o[OFF_ANG + (tid - T_ANG0)] = acosf(ct);
    }
    else if (tid >= T_DIH0 && tid < T_DIH0 + NF_DIH) {
        // ---- dihedrals (cos+sin fused): warp 9 ----
        const int d  = tid - T_DIH0;
        const int d3 = d * 3;

        const float ax = sraw[d3 + 3] - sraw[d3 + 0];
        const float ay = sraw[d3 + 4] - sraw[d3 + 1];
        const float az = sraw[d3 + 5] - sraw[d3 + 2];
        const float bx = sraw[d3 + 6] - sraw[d3 + 3];
        const float by = sraw[d3 + 7] - sraw[d3 + 4];
        const float bz = sraw[d3 + 8] - sraw[d3 + 5];
        const float cx = sraw[d3 + 9] - sraw[d3 + 6];
        const float cy = sraw[d3 +10] - sraw[d3 + 7];
        const float cz = sraw[d3 +11] - sraw[d3 + 8];

        const float p1x = ay * bz - az * by;
        const float p1y = az * bx - ax * bz;
        const float p1z = ax * by - ay * bx;
        const float p2x = by * cz - bz * cy;
        const float p2y = bz * cx - bx * cz;
        const float p2z = bx * cy - by * cx;

        const float n1sq  = fmaf(p1x, p1x, fmaf(p1y, p1y, p1z * p1z));
        const float n2sq  = fmaf(p2x, p2x, fmaf(p2y, p2y, p2z * p2z));
        const float inv12 = rsqrtf(n1sq * n2sq);

        const float dp = fmaf(p1x, p2x, fmaf(p1y, p2y, p1z * p2z));
        o[OFF_DCOS + d] = dp * inv12;

        const float qx = p1y * p2z - p1z * p2y;
        const float qy = p1z * p2x - p1x * p2z;
        const float qz = p1x * p2y - p1y * p2x;
        const float num  = fmaf(qx, bx, fmaf(qy, by, qz * bz));
        const float bnsq = fmaf(bx, bx, fmaf(by, by, bz * bz));
        o[OFF_DSIN + d] = num * inv12 * rsqrtf(bnsq);
    }
}

extern "C" void kernel_launch(void* const* d_in, const int* in_sizes, int n_in,
                              void* d_out, int out_size)
{
    const float* data = (const float*)d_in[0];
    float* out = (float*)d_out;
    const int n_frames = in_sizes[0] / (NB * 3);

    protein_feat_kernel<<<n_frames, NTHREADS>>>(data, out);
}